// round 4
// baseline (speedup 1.0000x reference)
#include <cuda_runtime.h>

#define BN 64
#define CN 32
#define HN 80
#define WN 80
#define LN 6400
#define HEADSN 8
#define NCH 25
#define CHK 256
#define INV_PI 0.31830988618379067f

// ---------------- device scratch (static: no allocations allowed) ----------------
static __device__ float g_vbuf[(size_t)BN * LN * CN];       // LA v, (B,L,32)
static __device__ float g_f1[(size_t)BN * CN * LN];         // LA branch out, (B,C,L)
static __device__ float g_f2[(size_t)BN * CN * LN];         // XCA branch out, (B,C,L)
static __device__ float g_part_la[BN * NCH * HEADSN * 16];
static __device__ float g_attn_la[BN * HEADSN * 16];
static __device__ float g_part_x[BN * NCH * HEADSN * 24];
static __device__ float g_attn_x[BN * HEADSN * 16];
static __device__ float g_pool_avg[2 * BN * CN];
static __device__ float g_pool_max[2 * BN * CN];
static __device__ float g_s1[BN * CN * CN];
static __device__ float g_s2[BN * CN * CN];
static __device__ float g_pooled1[BN * 2 * LN];
static __device__ float g_pooled2[BN * 2 * LN];
static __device__ float g_y1a[BN * LN];
static __device__ float g_y1b[BN * LN];
static __device__ float g_y2a[BN * LN];
static __device__ float g_y2b[BN * LN];
static __device__ float g_gstat[BN * 2 * 2];

// ---------------- K1: LA pass1 — per-chunk k-hat (x) v Gram partials + store v ----------------
__global__ __launch_bounds__(256) void k_la_pass1(const float* __restrict__ rgb,
                                                  const float* __restrict__ qkvw) {
    __shared__ float wsh[64 * 32];     // qkv rows 32..95 (k, v)
    __shared__ float vsh[CHK * 33];    // padded stride 33: bank-conflict-free
    __shared__ float accsh[8][HEADSN][16];
    const int b = blockIdx.y, ch = blockIdx.x, tid = threadIdx.x;
    const int warp = tid >> 5, lane = tid & 31;
    for (int i = tid; i < 64 * 32; i += 256) wsh[i] = qkvw[32 * 32 + i];
    __syncthreads();
    const int l = ch * CHK + tid;
    float x[32];
    const float* xr = rgb + (size_t)b * CN * LN + l;
#pragma unroll
    for (int c = 0; c < 32; c++) x[c] = xr[(size_t)c * LN];
#pragma unroll
    for (int h = 0; h < HEADSN; h++) {
        float k[4], v[4];
#pragma unroll
        for (int d = 0; d < 4; d++) {
            const float* wk = &wsh[(h * 4 + d) * 32];
            const float* wv = &wsh[(32 + h * 4 + d) * 32];
            float sk = 0.f, sv = 0.f;
#pragma unroll
            for (int c = 0; c < 32; c++) { sk += wk[c] * x[c]; sv += wv[c] * x[c]; }
            k[d] = sk; v[d] = sv;
        }
        float kn = rsqrtf(k[0]*k[0] + k[1]*k[1] + k[2]*k[2] + k[3]*k[3]);
#pragma unroll
        for (int e = 0; e < 4; e++) vsh[tid * 33 + h * 4 + e] = v[e];
        float p[16];
#pragma unroll
        for (int d = 0; d < 4; d++)
#pragma unroll
            for (int e = 0; e < 4; e++) p[d * 4 + e] = (k[d] * kn) * v[e];
#pragma unroll
        for (int i = 0; i < 16; i++) {
#pragma unroll
            for (int off = 16; off > 0; off >>= 1)
                p[i] += __shfl_xor_sync(0xffffffffu, p[i], off);
        }
        if (lane < 16) accsh[warp][h][lane] = p[lane];
    }
    __syncthreads();
    if (tid < 128) {
        const int h = tid >> 4, de = tid & 15;
        float s = 0.f;
#pragma unroll
        for (int w = 0; w < 8; w++) s += accsh[w][h][de];
        g_part_la[((size_t)(b * NCH + ch) * HEADSN + h) * 16 + de] = s;
    }
    float* vg = g_vbuf + ((size_t)b * LN + (size_t)ch * CHK) * 32;
    for (int i = tid; i < CHK * 32; i += 256) {
        int r = i >> 5, cc = i & 31;
        vg[i] = vsh[r * 33 + cc];
    }
}

// ---------------- K2: reduce LA Gram partials (deterministic fixed order) ----------------
__global__ void k_la_reduce() {
    int i = blockIdx.x * blockDim.x + threadIdx.x;
    if (i >= BN * HEADSN * 16) return;
    int b = i >> 7, r = i & 127;
    float s = 0.f;
    for (int ch = 0; ch < NCH; ch++) s += g_part_la[(size_t)(b * NCH + ch) * 128 + r];
    g_attn_la[i] = s;
}

// ---------------- K3: LA pass2 — q-hat @ attn, normalize, dconv from v halo, proj -> f1 ----------------
__global__ __launch_bounds__(256) void k_la_pass2(const float* __restrict__ rgb,
                                                  const float* __restrict__ qkvw,
                                                  const float* __restrict__ pw,
                                                  const float* __restrict__ pb,
                                                  const float* __restrict__ dw) {
    __shared__ float qsh[32 * 32];
    __shared__ float projsh[32 * 32];
    __shared__ float attnsh[HEADSN * 16];
    __shared__ float pbsh[32];
    __shared__ float dwsh[HEADSN * 9];
    __shared__ float vsh[264 * 33];     // 256 + 8 halo rows, padded stride
    const int b = blockIdx.y, ch = blockIdx.x, tid = threadIdx.x;
    for (int i = tid; i < 1024; i += 256) { qsh[i] = qkvw[i]; projsh[i] = pw[i]; }
    if (tid < 128) attnsh[tid] = g_attn_la[b * 128 + tid];
    if (tid < 32) pbsh[tid] = pb[tid];
    if (tid < 72) dwsh[tid] = dw[tid];
    const int l0 = ch * CHK;
    for (int i = tid; i < 264 * 32; i += 256) {
        int r = i >> 5, cc = i & 31;
        int gl = l0 - 4 + r;
        vsh[r * 33 + cc] = (gl >= 0 && gl < LN) ? g_vbuf[((size_t)b * LN + gl) * 32 + cc] : 0.f;
    }
    __syncthreads();
    const int l = l0 + tid;
    float x[32];
    const float* xr = rgb + (size_t)b * CN * LN + l;
#pragma unroll
    for (int c = 0; c < 32; c++) x[c] = xr[(size_t)c * LN];
    float out[32];
#pragma unroll
    for (int h = 0; h < HEADSN; h++) {
        float q[4];
#pragma unroll
        for (int d = 0; d < 4; d++) {
            const float* wq = &qsh[(h * 4 + d) * 32];
            float s = 0.f;
#pragma unroll
            for (int c = 0; c < 32; c++) s += wq[c] * x[c];
            q[d] = s;
        }
        float qn = rsqrtf(q[0]*q[0] + q[1]*q[1] + q[2]*q[2] + q[3]*q[3]);
        float o[4];
#pragma unroll
        for (int e = 0; e < 4; e++) {
            float t = 0.f;
#pragma unroll
            for (int d = 0; d < 4; d++) t += q[d] * attnsh[h * 16 + d * 4 + e];
            o[e] = 0.5f * vsh[(tid + 4) * 33 + h * 4 + e] + INV_PI * qn * t;
        }
        float on = rsqrtf(o[0]*o[0] + o[1]*o[1] + o[2]*o[2] + o[3]*o[3]);
#pragma unroll
        for (int e = 0; e < 4; e++) {
            float dc = 0.f;
#pragma unroll
            for (int t9 = 0; t9 < 9; t9++)
                dc += dwsh[h * 9 + t9] * vsh[(tid + t9) * 33 + h * 4 + e];
            out[h * 4 + e] = o[e] * on + dc;
        }
    }
#pragma unroll
    for (int c = 0; c < 32; c++) {
        const float* wp = &projsh[c * 32];
        float s = pbsh[c];
#pragma unroll
        for (int j = 0; j < 32; j++) s += wp[j] * out[j];
        g_f1[(size_t)b * CN * LN + (size_t)c * LN + l] = s;
    }
}

// ---------------- K4: XCA pass1 — q.k Gram + L2-norm partials over L ----------------
__global__ __launch_bounds__(256) void k_xca_pass1(const float* __restrict__ freq,
                                                   const float* __restrict__ qkvw) {
    __shared__ float wsh[64 * 32];  // qkv rows 0..63 (q, k)
    __shared__ float accsh[8][HEADSN][24];
    const int b = blockIdx.y, ch = blockIdx.x, tid = threadIdx.x;
    const int warp = tid >> 5, lane = tid & 31;
    for (int i = tid; i < 64 * 32; i += 256) wsh[i] = qkvw[i];
    __syncthreads();
    const int l = ch * CHK + tid;
    float x[32];
    const float* xr = freq + (size_t)b * CN * LN + l;
#pragma unroll
    for (int c = 0; c < 32; c++) x[c] = xr[(size_t)c * LN];
#pragma unroll
    for (int h = 0; h < HEADSN; h++) {
        float q[4], k[4];
#pragma unroll
        for (int d = 0; d < 4; d++) {
            const float* wq = &wsh[(h * 4 + d) * 32];
            const float* wk = &wsh[(32 + h * 4 + d) * 32];
            float sq = 0.f, sk = 0.f;
#pragma unroll
            for (int c = 0; c < 32; c++) { sq += wq[c] * x[c]; sk += wk[c] * x[c]; }
            q[d] = sq; k[d] = sk;
        }
        float p[24];
#pragma unroll
        for (int d = 0; d < 4; d++)
#pragma unroll
            for (int e = 0; e < 4; e++) p[d * 4 + e] = q[d] * k[e];
#pragma unroll
        for (int d = 0; d < 4; d++) { p[16 + d] = q[d] * q[d]; p[20 + d] = k[d] * k[d]; }
#pragma unroll
        for (int i = 0; i < 24; i++) {
#pragma unroll
            for (int off = 16; off > 0; off >>= 1)
                p[i] += __shfl_xor_sync(0xffffffffu, p[i], off);
        }
        if (lane < 24) accsh[warp][h][lane] = p[lane];
    }
    __syncthreads();
    if (tid < 192) {
        const int h = tid / 24, j = tid % 24;
        float s = 0.f;
#pragma unroll
        for (int w = 0; w < 8; w++) s += accsh[w][h][j];
        g_part_x[((size_t)(b * NCH + ch) * HEADSN + h) * 24 + j] = s;
    }
}

// ---------------- K5: XCA attn = softmax(Gram / (||q|| ||k||) * temp) ----------------
__global__ void k_xca_attn(const float* __restrict__ temp) {
    int i = blockIdx.x * blockDim.x + threadIdx.x;
    if (i >= BN * HEADSN) return;
    int b = i >> 3, h = i & 7;
    float s[24];
#pragma unroll
    for (int j = 0; j < 24; j++) s[j] = 0.f;
    for (int ch = 0; ch < NCH; ch++)
        for (int j = 0; j < 24; j++)
            s[j] += g_part_x[((size_t)(b * NCH + ch) * HEADSN + h) * 24 + j];
    float nq[4], nk[4];
#pragma unroll
    for (int d = 0; d < 4; d++) {
        nq[d] = fmaxf(sqrtf(s[16 + d]), 1e-12f);
        nk[d] = fmaxf(sqrtf(s[20 + d]), 1e-12f);
    }
    float t = temp[h];
#pragma unroll
    for (int d = 0; d < 4; d++) {
        float a[4], m = -1e30f;
#pragma unroll
        for (int e = 0; e < 4; e++) { a[e] = s[d * 4 + e] / (nq[d] * nk[e]) * t; m = fmaxf(m, a[e]); }
        float sum = 0.f;
#pragma unroll
        for (int e = 0; e < 4; e++) { a[e] = expf(a[e] - m); sum += a[e]; }
        float inv = 1.f / sum;
#pragma unroll
        for (int e = 0; e < 4; e++) g_attn_x[(size_t)(b * HEADSN + h) * 16 + d * 4 + e] = a[e] * inv;
    }
}

// ---------------- K6: XCA pass2 — attn @ v, proj -> f2 ----------------
__global__ __launch_bounds__(256) void k_xca_pass2(const float* __restrict__ freq,
                                                   const float* __restrict__ qkvw,
                                                   const float* __restrict__ pw,
                                                   const float* __restrict__ pb) {
    __shared__ float vwsh[32 * 32];  // qkv rows 64..95 (v)
    __shared__ float projsh[32 * 32];
    __shared__ float attnsh[128];
    __shared__ float pbsh[32];
    const int b = blockIdx.y, ch = blockIdx.x, tid = threadIdx.x;
    for (int i = tid; i < 1024; i += 256) { vwsh[i] = qkvw[64 * 32 + i]; projsh[i] = pw[i]; }
    if (tid < 128) attnsh[tid] = g_attn_x[(size_t)b * 128 + tid];
    if (tid < 32) pbsh[tid] = pb[tid];
    __syncthreads();
    const int l = ch * CHK + tid;
    float x[32];
    const float* xr = freq + (size_t)b * CN * LN + l;
#pragma unroll
    for (int c = 0; c < 32; c++) x[c] = xr[(size_t)c * LN];
    float out[32];
#pragma unroll
    for (int h = 0; h < HEADSN; h++) {
        float v[4];
#pragma unroll
        for (int e = 0; e < 4; e++) {
            const float* wv = &vwsh[(h * 4 + e) * 32];
            float sv = 0.f;
#pragma unroll
            for (int c = 0; c < 32; c++) sv += wv[c] * x[c];
            v[e] = sv;
        }
#pragma unroll
        for (int d = 0; d < 4; d++) {
            float o = 0.f;
#pragma unroll
            for (int e = 0; e < 4; e++) o += attnsh[h * 16 + d * 4 + e] * v[e];
            out[h * 4 + d] = o;
        }
    }
#pragma unroll
    for (int c = 0; c < 32; c++) {
        const float* wp = &projsh[c * 32];
        float s = pbsh[c];
#pragma unroll
        for (int j = 0; j < 32; j++) s += wp[j] * out[j];
        g_f2[(size_t)b * CN * LN + (size_t)c * LN + l] = s;
    }
}

// ---------------- K7: channel avg/max pooling over L for f1 and f2 ----------------
__global__ __launch_bounds__(256) void k_pool() {
    const int bc = blockIdx.x, src = blockIdx.y, tid = threadIdx.x;
    const float* f = (src ? g_f2 : g_f1) + (size_t)bc * LN;
    const float4* f4 = (const float4*)f;
    float s = 0.f, m = -1e30f;
    for (int i = tid; i < LN / 4; i += 256) {
        float4 v = f4[i];
        s += v.x + v.y + v.z + v.w;
        m = fmaxf(m, fmaxf(fmaxf(v.x, v.y), fmaxf(v.z, v.w)));
    }
    __shared__ float ssh[256], msh[256];
    ssh[tid] = s; msh[tid] = m;
    __syncthreads();
    for (int o = 128; o > 0; o >>= 1) {
        if (tid < o) { ssh[tid] += ssh[tid + o]; msh[tid] = fmaxf(msh[tid], msh[tid + o]); }
        __syncthreads();
    }
    if (tid == 0) {
        g_pool_avg[src * BN * CN + bc] = ssh[0] * (1.f / LN);
        g_pool_max[src * BN * CN + bc] = msh[0];
    }
}

// ---------------- K8: channel MLPs -> a1,a2; softmax rows of cross / cross^T ----------------
__global__ void k_cafm_vec(const float* __restrict__ a1w, const float* __restrict__ a1b,
                           const float* __restrict__ m1w, const float* __restrict__ m1b,
                           const float* __restrict__ a2w, const float* __restrict__ a2b,
                           const float* __restrict__ m2w, const float* __restrict__ m2b,
                           const float* __restrict__ a11w, const float* __restrict__ a11b,
                           const float* __restrict__ m11w, const float* __restrict__ m11b,
                           const float* __restrict__ a22w, const float* __restrict__ a22b,
                           const float* __restrict__ m22w, const float* __restrict__ m22b) {
    const int b = blockIdx.x, c = threadIdx.x;  // 32 threads
    __shared__ float av1[32], mx1[32], av2[32], mx2[32];
    __shared__ float h1a[16], h1m[16], h2a[16], h2m[16];
    __shared__ float a1s[32], a2s[32];
    av1[c] = g_pool_avg[b * 32 + c];
    mx1[c] = g_pool_max[b * 32 + c];
    av2[c] = g_pool_avg[BN * CN + b * 32 + c];
    mx2[c] = g_pool_max[BN * CN + b * 32 + c];
    __syncthreads();
    if (c < 16) {
        float s1 = a1b[c], s2 = m1b[c], s3 = a2b[c], s4 = m2b[c];
        for (int j = 0; j < 32; j++) {
            s1 += a1w[c * 32 + j] * av1[j];
            s2 += m1w[c * 32 + j] * mx1[j];
            s3 += a2w[c * 32 + j] * av2[j];
            s4 += m2w[c * 32 + j] * mx2[j];
        }
        h1a[c] = fmaxf(s1, 0.f); h1m[c] = fmaxf(s2, 0.f);
        h2a[c] = fmaxf(s3, 0.f); h2m[c] = fmaxf(s4, 0.f);
    }
    __syncthreads();
    {
        float s1 = a11b[c] + m11b[c];
        float s2 = a22b[c] + m22b[c];
        for (int j = 0; j < 16; j++) {
            s1 += a11w[c * 16 + j] * h1a[j] + m11w[c * 16 + j] * h1m[j];
            s2 += a22w[c * 16 + j] * h2a[j] + m22w[c * 16 + j] * h2m[j];
        }
        a1s[c] = s1; a2s[c] = s2;
    }
    __syncthreads();
    {
        float ac = a1s[c], m = -1e30f;
        for (int d = 0; d < 32; d++) m = fmaxf(m, ac * a2s[d]);
        float sum = 0.f;
        for (int d = 0; d < 32; d++) sum += expf(ac * a2s[d] - m);
        float inv = 1.f / sum;
        for (int d = 0; d < 32; d++) g_s1[(size_t)b * 1024 + c * 32 + d] = expf(ac * a2s[d] - m) * inv;
    }
    {
        float ac = a2s[c], m = -1e30f;
        for (int d = 0; d < 32; d++) m = fmaxf(m, ac * a1s[d]);
        float sum = 0.f;
        for (int d = 0; d < 32; d++) sum += expf(ac * a1s[d] - m);
        float inv = 1.f / sum;
        for (int d = 0; d < 32; d++) g_s2[(size_t)b * 1024 + c * 32 + d] = expf(ac * a1s[d] - m) * inv;
    }
}

// ---------------- K9: fused s@f + mean/max over C -> spatial-gate pooled inputs ----------------
__global__ __launch_bounds__(256) void k_gate_pool() {
    __shared__ float s1sh[1024], s2sh[1024];
    const int b = blockIdx.y, ch = blockIdx.x, tid = threadIdx.x;
    for (int i = tid; i < 1024; i += 256) {
        s1sh[i] = g_s1[(size_t)b * 1024 + i];
        s2sh[i] = g_s2[(size_t)b * 1024 + i];
    }
    __syncthreads();
    const int l = ch * CHK + tid;
    float f1c[32], f2c[32];
#pragma unroll
    for (int d = 0; d < 32; d++) {
        f1c[d] = g_f1[(size_t)b * CN * LN + (size_t)d * LN + l];
        f2c[d] = g_f2[(size_t)b * CN * LN + (size_t)d * LN + l];
    }
    float sum1 = 0.f, max1 = -1e30f, sum2 = 0.f, max2 = -1e30f;
#pragma unroll 4
    for (int c = 0; c < 32; c++) {
        float a1 = 0.f, a2 = 0.f;
#pragma unroll
        for (int d = 0; d < 32; d++) { a1 += s1sh[c * 32 + d] * f1c[d]; a2 += s2sh[c * 32 + d] * f2c[d]; }
        sum1 += a1; max1 = fmaxf(max1, a1);
        sum2 += a2; max2 = fmaxf(max2, a2);
    }
    g_pooled1[(size_t)b * 2 * LN + l] = sum1 * (1.f / 32.f);
    g_pooled1[(size_t)b * 2 * LN + LN + l] = max1;
    g_pooled2[(size_t)b * 2 * LN + l] = sum2 * (1.f / 32.f);
    g_pooled2[(size_t)b * 2 * LN + LN + l] = max2;
}

// ---------------- K10/K11: 3x3 convs of the spatial gate ----------------
__global__ __launch_bounds__(256) void k_conv1(const float* __restrict__ w, const float* __restrict__ bias) {
    const int b = blockIdx.x, gate = blockIdx.y, tid = threadIdx.x;
    const float* pin = (gate ? g_pooled2 : g_pooled1) + (size_t)b * 2 * LN;
    float* yo = (gate ? g_y1b : g_y1a) + (size_t)b * LN;
    float wr[18];
#pragma unroll
    for (int i = 0; i < 18; i++) wr[i] = w[i];
    float bv = bias[0];
    for (int p = tid; p < LN; p += 256) {
        int hh = p / WN, ww = p % WN;
        float acc = bv;
#pragma unroll
        for (int ci = 0; ci < 2; ci++)
#pragma unroll
            for (int kh = 0; kh < 3; kh++) {
                int ih = hh + kh - 1;
                if (ih < 0 || ih >= HN) continue;
#pragma unroll
                for (int kw = 0; kw < 3; kw++) {
                    int iw = ww + kw - 1;
                    if (iw < 0 || iw >= WN) continue;
                    acc += pin[(size_t)ci * LN + ih * WN + iw] * wr[(ci * 3 + kh) * 3 + kw];
                }
            }
        yo[p] = fmaxf(acc, 0.f);
    }
}

__global__ __launch_bounds__(256) void k_conv2(const float* __restrict__ w, const float* __restrict__ bias) {
    const int b = blockIdx.x, gate = blockIdx.y, tid = threadIdx.x;
    const float* yin = (gate ? g_y1b : g_y1a) + (size_t)b * LN;
    float* yo = (gate ? g_y2b : g_y2a) + (size_t)b * LN;
    float wr[9];
#pragma unroll
    for (int i = 0; i < 9; i++) wr[i] = w[i];
    float bv = bias[0];
    for (int p = tid; p < LN; p += 256) {
        int hh = p / WN, ww = p % WN;
        float acc = bv;
#pragma unroll
        for (int kh = 0; kh < 3; kh++) {
            int ih = hh + kh - 1;
            if (ih < 0 || ih >= HN) continue;
#pragma unroll
            for (int kw = 0; kw < 3; kw++) {
                int iw = ww + kw - 1;
                if (iw < 0 || iw >= WN) continue;
                acc += yin[ih * WN + iw] * wr[kh * 3 + kw];
            }
        }
        yo[p] = acc;
    }
}

// ---------------- K12: per-(b,gate) softmax stats over L ----------------
__global__ __launch_bounds__(256) void k_gstat() {
    const int b = blockIdx.x, gate = blockIdx.y, tid = threadIdx.x;
    const float* y = (gate ? g_y2b : g_y2a) + (size_t)b * LN;
    __shared__ float sh[256];
    float m = -1e30f;
    for (int i = tid; i < LN; i += 256) m = fmaxf(m, y[i]);
    sh[tid] = m;
    __syncthreads();
    for (int o = 128; o > 0; o >>= 1) { if (tid < o) sh[tid] = fmaxf(sh[tid], sh[tid + o]); __syncthreads(); }
    float gm = sh[0];
    __syncthreads();
    float s = 0.f;
    for (int i = tid; i < LN; i += 256) s += expf(y[i] - gm);
    sh[tid] = s;
    __syncthreads();
    for (int o = 128; o > 0; o >>= 1) { if (tid < o) sh[tid] += sh[tid + o]; __syncthreads(); }
    if (tid == 0) { g_gstat[(b * 2 + gate) * 2] = gm; g_gstat[(b * 2 + gate) * 2 + 1] = sh[0]; }
}

// ---------------- K13: final gated residual combine, float4 ----------------
__global__ __launch_bounds__(256) void k_final(float* __restrict__ out) {
    const int NT4 = BN * CN * LN / 4;
    int i4 = blockIdx.x * 256 + threadIdx.x;
    if (i4 >= NT4) return;
    size_t i = (size_t)i4 * 4;
    int b = (int)(i / (CN * LN));
    int rem = (int)(i - (size_t)b * CN * LN);
    int l = rem % LN;
    float4 f1v = *(const float4*)(g_f1 + i);
    float4 f2v = *(const float4*)(g_f2 + i);
    float4 y1v = *(const float4*)(g_y2a + (size_t)b * LN + l);
    float4 y2v = *(const float4*)(g_y2b + (size_t)b * LN + l);
    float m1 = g_gstat[b * 4 + 0], s1i = 1.f / g_gstat[b * 4 + 1];
    float m2 = g_gstat[b * 4 + 2], s2i = 1.f / g_gstat[b * 4 + 3];
    float4 o;
    o.x = f1v.x * (1.f + expf(y1v.x - m1) * s1i) + f2v.x * (1.f + expf(y2v.x - m2) * s2i);
    o.y = f1v.y * (1.f + expf(y1v.y - m1) * s1i) + f2v.y * (1.f + expf(y2v.y - m2) * s2i);
    o.z = f1v.z * (1.f + expf(y1v.z - m1) * s1i) + f2v.z * (1.f + expf(y2v.z - m2) * s2i);
    o.w = f1v.w * (1.f + expf(y1v.w - m1) * s1i) + f2v.w * (1.f + expf(y2v.w - m2) * s2i);
    *(float4*)(out + i) = o;
}

// ---------------- launch ----------------
extern "C" void kernel_launch(void* const* d_in, const int* in_sizes, int n_in,
                              void* d_out, int out_size) {
    const float* rgb     = (const float*)d_in[0];
    const float* freq    = (const float*)d_in[1];
    const float* la_qkv  = (const float*)d_in[2];
    const float* la_pw   = (const float*)d_in[3];
    const float* la_pb   = (const float*)d_in[4];
    const float* la_dw   = (const float*)d_in[5];
    const float* xa_qkv  = (const float*)d_in[6];
    const float* xa_temp = (const float*)d_in[7];
    const float* xa_pw   = (const float*)d_in[8];
    const float* xa_pb   = (const float*)d_in[9];
    const float* c1w     = (const float*)d_in[10];
    const float* c1b     = (const float*)d_in[11];
    const float* c2w     = (const float*)d_in[12];
    const float* c2b     = (const float*)d_in[13];
    const float* avg1_w  = (const float*)d_in[14];
    const float* avg1_b  = (const float*)d_in[15];
    const float* max1_w  = (const float*)d_in[16];
    const float* max1_b  = (const float*)d_in[17];
    const float* avg2_w  = (const float*)d_in[18];
    const float* avg2_b  = (const float*)d_in[19];
    const float* max2_w  = (const float*)d_in[20];
    const float* max2_b  = (const float*)d_in[21];
    const float* avg11_w = (const float*)d_in[22];
    const float* avg11_b = (const float*)d_in[23];
    const float* max11_w = (const float*)d_in[24];
    const float* max11_b = (const float*)d_in[25];
    const float* avg22_w = (const float*)d_in[26];
    const float* avg22_b = (const float*)d_in[27];
    const float* max22_w = (const float*)d_in[28];
    const float* max22_b = (const float*)d_in[29];
    float* out = (float*)d_out;

    dim3 gBL(NCH, BN);
    k_la_pass1<<<gBL, 256>>>(rgb, la_qkv);
    k_la_reduce<<<(BN * HEADSN * 16 + 255) / 256, 256>>>();
    k_la_pass2<<<gBL, 256>>>(rgb, la_qkv, la_pw, la_pb, la_dw);
    k_xca_pass1<<<gBL, 256>>>(freq, xa_qkv);
    k_xca_attn<<<2, 256>>>(xa_temp);
    k_xca_pass2<<<gBL, 256>>>(freq, xa_qkv, xa_pw, xa_pb);
    k_pool<<<dim3(BN * CN, 2), 256>>>();
    k_cafm_vec<<<BN, 32>>>(avg1_w, avg1_b, max1_w, max1_b,
                           avg2_w, avg2_b, max2_w, max2_b,
                           avg11_w, avg11_b, max11_w, max11_b,
                           avg22_w, avg22_b, max22_w, max22_b);
    k_gate_pool<<<gBL, 256>>>();
    k_conv1<<<dim3(BN, 2), 256>>>(c1w, c1b);
    k_conv2<<<dim3(BN, 2), 256>>>(c2w, c2b);
    k_gstat<<<dim3(BN, 2), 256>>>();
    k_final<<<(BN * CN * LN / 4 + 255) / 256, 256>>>(out);
}

// round 5
// speedup vs baseline: 1.0537x; 1.0537x over previous
#include <cuda_runtime.h>

#define BN 64
#define CN 32
#define HN 80
#define WN 80
#define LN 6400
#define HEADSN 8
#define NCH 25
#define CHK 256
#define INV_PI 0.31830988618379067f

typedef unsigned long long u64;

__device__ __forceinline__ u64 pk2(float lo, float hi) {
    u64 r; asm("mov.b64 %0,{%1,%2};" : "=l"(r) : "f"(lo), "f"(hi)); return r;
}
__device__ __forceinline__ void upk2(u64 a, float& lo, float& hi) {
    asm("mov.b64 {%0,%1},%2;" : "=f"(lo), "=f"(hi) : "l"(a));
}
__device__ __forceinline__ u64 fma2_(u64 a, u64 b, u64 c) {
    u64 d; asm("fma.rn.f32x2 %0,%1,%2,%3;" : "=l"(d) : "l"(a), "l"(b), "l"(c)); return d;
}
__device__ __forceinline__ u64 add2_(u64 a, u64 b) {
    u64 d; asm("add.rn.f32x2 %0,%1,%2;" : "=l"(d) : "l"(a), "l"(b)); return d;
}
__device__ __forceinline__ u64 mul2_(u64 a, u64 b) {
    u64 d; asm("mul.rn.f32x2 %0,%1,%2;" : "=l"(d) : "l"(a), "l"(b)); return d;
}

// ---------------- device scratch ----------------
static __device__ float g_vbuf[(size_t)BN * LN * CN];
static __device__ float g_f1[(size_t)BN * CN * LN];
static __device__ float g_f2[(size_t)BN * CN * LN];
static __device__ float g_part_la[BN * NCH * HEADSN * 16];
static __device__ float g_attn_la[BN * HEADSN * 16];
static __device__ float g_part_x[BN * NCH * HEADSN * 24];
static __device__ float g_attn_x[BN * HEADSN * 16];
static __device__ float g_pf_sum[2 * BN * NCH * 32];
static __device__ float g_pf_max[2 * BN * NCH * 32];
static __device__ float g_s1[BN * CN * CN];
static __device__ float g_s2[BN * CN * CN];
static __device__ float g_pooled1[BN * 2 * LN];
static __device__ float g_pooled2[BN * 2 * LN];
static __device__ float g_y1a[BN * LN];
static __device__ float g_y1b[BN * LN];
static __device__ float g_y2a[BN * LN];
static __device__ float g_y2b[BN * LN];
static __device__ float g_gstat[BN * 2 * 2];

// ---------------- K1: LA pass1 — packed khat(x)v Gram partials + store v ----------------
__global__ __launch_bounds__(128) void k_la_pass1(const float* __restrict__ rgb,
                                                  const float* __restrict__ qkvw) {
    __shared__ __align__(16) u64 wdup[64 * 32];   // k rows (0..31) + v rows (32..63), duplicated
    __shared__ float accsh[4][HEADSN][16];
    const int b = blockIdx.y, ch = blockIdx.x, tid = threadIdx.x;
    const int warp = tid >> 5, lane = tid & 31;
    for (int i = tid; i < 64 * 32; i += 128) { float w = qkvw[32 * 32 + i]; wdup[i] = pk2(w, w); }
    __syncthreads();
    const int l0 = ch * CHK + tid, l1 = l0 + 128;
    const float* xr = rgb + (size_t)b * CN * LN;
    u64 xp[32];
#pragma unroll
    for (int c = 0; c < 32; c++) xp[c] = pk2(xr[(size_t)c * LN + l0], xr[(size_t)c * LN + l1]);
    float* vg0 = g_vbuf + ((size_t)b * LN + l0) * 32;
    float* vg1 = g_vbuf + ((size_t)b * LN + l1) * 32;
#pragma unroll
    for (int h = 0; h < HEADSN; h++) {
        u64 kp[4], vp[4];
#pragma unroll
        for (int d = 0; d < 4; d++) {
            const u64* wk = &wdup[(h * 4 + d) * 32];
            const u64* wv = &wdup[(32 + h * 4 + d) * 32];
            u64 ak = 0ull, av = 0ull;
#pragma unroll
            for (int c = 0; c < 32; c++) { ak = fma2_(wk[c], xp[c], ak); av = fma2_(wv[c], xp[c], av); }
            kp[d] = ak; vp[d] = av;
        }
        float v0[4], v1[4];
#pragma unroll
        for (int e = 0; e < 4; e++) upk2(vp[e], v0[e], v1[e]);
        *(float4*)(vg0 + h * 4) = make_float4(v0[0], v0[1], v0[2], v0[3]);
        *(float4*)(vg1 + h * 4) = make_float4(v1[0], v1[1], v1[2], v1[3]);
        u64 ss = mul2_(kp[0], kp[0]);
        ss = fma2_(kp[1], kp[1], ss); ss = fma2_(kp[2], kp[2], ss); ss = fma2_(kp[3], kp[3], ss);
        float s0, s1; upk2(ss, s0, s1);
        u64 knp = pk2(rsqrtf(s0), rsqrtf(s1));
        float p[16];
#pragma unroll
        for (int d = 0; d < 4; d++) {
            u64 kh = mul2_(kp[d], knp);
#pragma unroll
            for (int e = 0; e < 4; e++) {
                float a, bb; upk2(mul2_(kh, vp[e]), a, bb);
                p[d * 4 + e] = a + bb;
            }
        }
#pragma unroll
        for (int i = 0; i < 16; i++)
#pragma unroll
            for (int off = 16; off > 0; off >>= 1)
                p[i] += __shfl_xor_sync(0xffffffffu, p[i], off);
        if (lane < 16) accsh[warp][h][lane] = p[lane];
    }
    __syncthreads();
    {
        const int h = tid >> 4, de = tid & 15;
        float s = accsh[0][h][de] + accsh[1][h][de] + accsh[2][h][de] + accsh[3][h][de];
        g_part_la[((size_t)(b * NCH + ch) * HEADSN + h) * 16 + de] = s;
    }
}

// ---------------- K2: reduce LA Gram partials ----------------
__global__ void k_la_reduce() {
    int i = blockIdx.x * blockDim.x + threadIdx.x;
    if (i >= BN * HEADSN * 16) return;
    int b = i >> 7, r = i & 127;
    float s = 0.f;
    for (int ch = 0; ch < NCH; ch++) s += g_part_la[(size_t)(b * NCH + ch) * 128 + r];
    g_attn_la[i] = s;
}

// ---------------- K3: LA pass2 (dynamic smem) ----------------
#define LA2_SMEM 57344
__global__ __launch_bounds__(128) void k_la_pass2(const float* __restrict__ rgb,
                                                  const float* __restrict__ qkvw,
                                                  const float* __restrict__ pw,
                                                  const float* __restrict__ pb,
                                                  const float* __restrict__ dw) {
    extern __shared__ __align__(16) char dynsm[];
    u64* qdup = (u64*)dynsm;                       // 1024 u64
    u64* projdup = qdup + 1024;                    // 1024 u64
    u64* attn_dup = projdup + 1024;                // 128 u64  (ends @17408B)
    float* vsh = (float*)(dynsm + 17408);          // 264*36 floats (38016B)
    float* dwsh = (float*)(dynsm + 55424);         // 72
    float* pbsh = dwsh + 72;                       // 32
    float* psum = pbsh + 32;                       // 128
    float* pmax = psum + 128;                      // 128
    const int b = blockIdx.y, ch = blockIdx.x, tid = threadIdx.x;
    const int warp = tid >> 5, lane = tid & 31;
    for (int i = tid; i < 1024; i += 128) {
        float a = qkvw[i]; qdup[i] = pk2(a, a);
        float p_ = pw[i]; projdup[i] = pk2(p_, p_);
    }
    { float a = g_attn_la[b * 128 + tid]; attn_dup[tid] = pk2(a, a); }
    if (tid < 72) dwsh[tid] = dw[tid];
    if (tid < 32) pbsh[tid] = pb[tid];
    const int l0b = ch * CHK;
    for (int i = tid; i < 264 * 8; i += 128) {
        int r = i >> 3, c4 = i & 7;
        int gl = l0b - 4 + r;
        float4 v = (gl >= 0 && gl < LN) ? *(const float4*)(g_vbuf + ((size_t)b * LN + gl) * 32 + c4 * 4)
                                        : make_float4(0.f, 0.f, 0.f, 0.f);
        *(float4*)(vsh + r * 36 + c4 * 4) = v;
    }
    __syncthreads();
    const int l0 = l0b + tid, l1 = l0 + 128;
    const float* xr = rgb + (size_t)b * CN * LN;
    u64 xp[32];
#pragma unroll
    for (int c = 0; c < 32; c++) xp[c] = pk2(xr[(size_t)c * LN + l0], xr[(size_t)c * LN + l1]);
    u64 qp[32];
#pragma unroll
    for (int r = 0; r < 32; r++) {
        const u64* w = &qdup[r * 32];
        u64 a = 0ull;
#pragma unroll
        for (int c = 0; c < 32; c++) a = fma2_(w[c], xp[c], a);
        qp[r] = a;
    }
    const u64 HALFP = pk2(0.5f, 0.5f);
    u64 outp[32];
#pragma unroll
    for (int h = 0; h < HEADSN; h++) {
        u64* q = &qp[h * 4];
        u64 ss = mul2_(q[0], q[0]);
        ss = fma2_(q[1], q[1], ss); ss = fma2_(q[2], q[2], ss); ss = fma2_(q[3], q[3], ss);
        float s0, s1; upk2(ss, s0, s1);
        u64 qnp = pk2(rsqrtf(s0) * INV_PI, rsqrtf(s1) * INV_PI);
        float4 vc0 = *(float4*)(vsh + (tid + 4) * 36 + h * 4);
        float4 vc1 = *(float4*)(vsh + (tid + 132) * 36 + h * 4);
        u64 op[4];
#pragma unroll
        for (int e = 0; e < 4; e++) {
            u64 t = mul2_(q[0], attn_dup[h * 16 + e]);
            t = fma2_(q[1], attn_dup[h * 16 + 4 + e], t);
            t = fma2_(q[2], attn_dup[h * 16 + 8 + e], t);
            t = fma2_(q[3], attn_dup[h * 16 + 12 + e], t);
            u64 vcp = pk2((&vc0.x)[e], (&vc1.x)[e]);
            op[e] = fma2_(qnp, t, mul2_(HALFP, vcp));
        }
        u64 os = mul2_(op[0], op[0]);
        os = fma2_(op[1], op[1], os); os = fma2_(op[2], op[2], os); os = fma2_(op[3], op[3], os);
        float o0, o1; upk2(os, o0, o1);
        u64 onp = pk2(rsqrtf(o0), rsqrtf(o1));
        float dc0[4] = {0.f, 0.f, 0.f, 0.f}, dc1[4] = {0.f, 0.f, 0.f, 0.f};
#pragma unroll
        for (int t9 = 0; t9 < 9; t9++) {
            float wd = dwsh[h * 9 + t9];
            float4 a0 = *(float4*)(vsh + (tid + t9) * 36 + h * 4);
            float4 a1 = *(float4*)(vsh + (tid + 128 + t9) * 36 + h * 4);
            dc0[0] += wd * a0.x; dc0[1] += wd * a0.y; dc0[2] += wd * a0.z; dc0[3] += wd * a0.w;
            dc1[0] += wd * a1.x; dc1[1] += wd * a1.y; dc1[2] += wd * a1.z; dc1[3] += wd * a1.w;
        }
#pragma unroll
        for (int e = 0; e < 4; e++)
            outp[h * 4 + e] = fma2_(op[e], onp, pk2(dc0[e], dc1[e]));
    }
#pragma unroll
    for (int c = 0; c < 32; c++) {
        const u64* w = &projdup[c * 32];
        u64 a = pk2(pbsh[c], pbsh[c]);
#pragma unroll
        for (int j = 0; j < 32; j++) a = fma2_(w[j], outp[j], a);
        float s0, s1; upk2(a, s0, s1);
        g_f1[(size_t)b * CN * LN + (size_t)c * LN + l0] = s0;
        g_f1[(size_t)b * CN * LN + (size_t)c * LN + l1] = s1;
        float sc = s0 + s1, mc = fmaxf(s0, s1);
#pragma unroll
        for (int off = 16; off > 0; off >>= 1) {
            sc += __shfl_xor_sync(0xffffffffu, sc, off);
            mc = fmaxf(mc, __shfl_xor_sync(0xffffffffu, mc, off));
        }
        if (lane == 0) { psum[warp * 32 + c] = sc; pmax[warp * 32 + c] = mc; }
    }
    __syncthreads();
    if (tid < 32) {
        float s = psum[tid] + psum[32 + tid] + psum[64 + tid] + psum[96 + tid];
        float m = fmaxf(fmaxf(pmax[tid], pmax[32 + tid]), fmaxf(pmax[64 + tid], pmax[96 + tid]));
        g_pf_sum[((size_t)b * NCH + ch) * 32 + tid] = s;
        g_pf_max[((size_t)b * NCH + ch) * 32 + tid] = m;
    }
}

// ---------------- K4: XCA pass1 — packed q.k Gram + norm partials ----------------
__global__ __launch_bounds__(128) void k_xca_pass1(const float* __restrict__ freq,
                                                   const float* __restrict__ qkvw) {
    __shared__ __align__(16) u64 wdup[64 * 32];   // q rows (0..31) + k rows (32..63)
    __shared__ float accsh[4][HEADSN][24];
    const int b = blockIdx.y, ch = blockIdx.x, tid = threadIdx.x;
    const int warp = tid >> 5, lane = tid & 31;
    for (int i = tid; i < 64 * 32; i += 128) { float w = qkvw[i]; wdup[i] = pk2(w, w); }
    __syncthreads();
    const int l0 = ch * CHK + tid, l1 = l0 + 128;
    const float* xr = freq + (size_t)b * CN * LN;
    u64 xp[32];
#pragma unroll
    for (int c = 0; c < 32; c++) xp[c] = pk2(xr[(size_t)c * LN + l0], xr[(size_t)c * LN + l1]);
#pragma unroll
    for (int h = 0; h < HEADSN; h++) {
        u64 qp[4], kp[4];
#pragma unroll
        for (int d = 0; d < 4; d++) {
            const u64* wq = &wdup[(h * 4 + d) * 32];
            const u64* wk = &wdup[(32 + h * 4 + d) * 32];
            u64 aq = 0ull, ak = 0ull;
#pragma unroll
            for (int c = 0; c < 32; c++) { aq = fma2_(wq[c], xp[c], aq); ak = fma2_(wk[c], xp[c], ak); }
            qp[d] = aq; kp[d] = ak;
        }
        float p[24];
#pragma unroll
        for (int d = 0; d < 4; d++)
#pragma unroll
            for (int e = 0; e < 4; e++) {
                float a, bb; upk2(mul2_(qp[d], kp[e]), a, bb);
                p[d * 4 + e] = a + bb;
            }
#pragma unroll
        for (int d = 0; d < 4; d++) {
            float a, bb;
            upk2(mul2_(qp[d], qp[d]), a, bb); p[16 + d] = a + bb;
            upk2(mul2_(kp[d], kp[d]), a, bb); p[20 + d] = a + bb;
        }
#pragma unroll
        for (int i = 0; i < 24; i++)
#pragma unroll
            for (int off = 16; off > 0; off >>= 1)
                p[i] += __shfl_xor_sync(0xffffffffu, p[i], off);
        if (lane < 24) accsh[warp][h][lane] = p[lane];
    }
    __syncthreads();
    for (int i = tid; i < HEADSN * 24; i += 128) {
        const int h = i / 24, j = i % 24;
        float s = accsh[0][h][j] + accsh[1][h][j] + accsh[2][h][j] + accsh[3][h][j];
        g_part_x[((size_t)(b * NCH + ch) * HEADSN + h) * 24 + j] = s;
    }
}

// ---------------- K5: XCA attn softmax ----------------
__global__ void k_xca_attn(const float* __restrict__ temp) {
    int i = blockIdx.x * blockDim.x + threadIdx.x;
    if (i >= BN * HEADSN) return;
    int b = i >> 3, h = i & 7;
    float s[24];
#pragma unroll
    for (int j = 0; j < 24; j++) s[j] = 0.f;
    for (int ch = 0; ch < NCH; ch++)
        for (int j = 0; j < 24; j++)
            s[j] += g_part_x[((size_t)(b * NCH + ch) * HEADSN + h) * 24 + j];
    float nq[4], nk[4];
#pragma unroll
    for (int d = 0; d < 4; d++) {
        nq[d] = fmaxf(sqrtf(s[16 + d]), 1e-12f);
        nk[d] = fmaxf(sqrtf(s[20 + d]), 1e-12f);
    }
    float t = temp[h];
#pragma unroll
    for (int d = 0; d < 4; d++) {
        float a[4], m = -1e30f;
#pragma unroll
        for (int e = 0; e < 4; e++) { a[e] = s[d * 4 + e] / (nq[d] * nk[e]) * t; m = fmaxf(m, a[e]); }
        float sum = 0.f;
#pragma unroll
        for (int e = 0; e < 4; e++) { a[e] = expf(a[e] - m); sum += a[e]; }
        float inv = 1.f / sum;
#pragma unroll
        for (int e = 0; e < 4; e++) g_attn_x[(size_t)(b * HEADSN + h) * 16 + d * 4 + e] = a[e] * inv;
    }
}

// ---------------- K6: XCA pass2 — packed attn@v + proj + pool fold ----------------
__global__ __launch_bounds__(128) void k_xca_pass2(const float* __restrict__ freq,
                                                   const float* __restrict__ qkvw,
                                                   const float* __restrict__ pw,
                                                   const float* __restrict__ pb) {
    __shared__ __align__(16) u64 vdup[1024];
    __shared__ __align__(16) u64 projdup[1024];
    __shared__ u64 attn_dup[128];
    __shared__ float pbsh[32], psum[128], pmax[128];
    const int b = blockIdx.y, ch = blockIdx.x, tid = threadIdx.x;
    const int warp = tid >> 5, lane = tid & 31;
    for (int i = tid; i < 1024; i += 128) {
        float a = qkvw[64 * 32 + i]; vdup[i] = pk2(a, a);
        float p_ = pw[i]; projdup[i] = pk2(p_, p_);
    }
    { float a = g_attn_x[(size_t)b * 128 + tid]; attn_dup[tid] = pk2(a, a); }
    if (tid < 32) pbsh[tid] = pb[tid];
    __syncthreads();
    const int l0 = ch * CHK + tid, l1 = l0 + 128;
    const float* xr = freq + (size_t)b * CN * LN;
    u64 xp[32];
#pragma unroll
    for (int c = 0; c < 32; c++) xp[c] = pk2(xr[(size_t)c * LN + l0], xr[(size_t)c * LN + l1]);
    u64 vp[32];
#pragma unroll
    for (int r = 0; r < 32; r++) {
        const u64* w = &vdup[r * 32];
        u64 a = 0ull;
#pragma unroll
        for (int c = 0; c < 32; c++) a = fma2_(w[c], xp[c], a);
        vp[r] = a;
    }
    u64 outp[32];
#pragma unroll
    for (int h = 0; h < HEADSN; h++) {
#pragma unroll
        for (int d = 0; d < 4; d++) {
            u64 o = mul2_(attn_dup[h * 16 + d * 4 + 0], vp[h * 4 + 0]);
            o = fma2_(attn_dup[h * 16 + d * 4 + 1], vp[h * 4 + 1], o);
            o = fma2_(attn_dup[h * 16 + d * 4 + 2], vp[h * 4 + 2], o);
            o = fma2_(attn_dup[h * 16 + d * 4 + 3], vp[h * 4 + 3], o);
            outp[h * 4 + d] = o;
        }
    }
#pragma unroll
    for (int c = 0; c < 32; c++) {
        const u64* w = &projdup[c * 32];
        u64 a = pk2(pbsh[c], pbsh[c]);
#pragma unroll
        for (int j = 0; j < 32; j++) a = fma2_(w[j], outp[j], a);
        float s0, s1; upk2(a, s0, s1);
        g_f2[(size_t)b * CN * LN + (size_t)c * LN + l0] = s0;
        g_f2[(size_t)b * CN * LN + (size_t)c * LN + l1] = s1;
        float sc = s0 + s1, mc = fmaxf(s0, s1);
#pragma unroll
        for (int off = 16; off > 0; off >>= 1) {
            sc += __shfl_xor_sync(0xffffffffu, sc, off);
            mc = fmaxf(mc, __shfl_xor_sync(0xffffffffu, mc, off));
        }
        if (lane == 0) { psum[warp * 32 + c] = sc; pmax[warp * 32 + c] = mc; }
    }
    __syncthreads();
    if (tid < 32) {
        float s = psum[tid] + psum[32 + tid] + psum[64 + tid] + psum[96 + tid];
        float m = fmaxf(fmaxf(pmax[tid], pmax[32 + tid]), fmaxf(pmax[64 + tid], pmax[96 + tid]));
        g_pf_sum[(size_t)(BN * NCH * 32) + ((size_t)b * NCH + ch) * 32 + tid] = s;
        g_pf_max[(size_t)(BN * NCH * 32) + ((size_t)b * NCH + ch) * 32 + tid] = m;
    }
}

// ---------------- K8: channel MLPs + cross softmax (pool reduce folded in) ----------------
__global__ void k_cafm_vec(const float* __restrict__ a1w, const float* __restrict__ a1b,
                           const float* __restrict__ m1w, const float* __restrict__ m1b,
                           const float* __restrict__ a2w, const float* __restrict__ a2b,
                           const float* __restrict__ m2w, const float* __restrict__ m2b,
                           const float* __restrict__ a11w, const float* __restrict__ a11b,
                           const float* __restrict__ m11w, const float* __restrict__ m11b,
                           const float* __restrict__ a22w, const float* __restrict__ a22b,
                           const float* __restrict__ m22w, const float* __restrict__ m22b) {
    const int b = blockIdx.x, c = threadIdx.x;  // 32 threads
    __shared__ float av1[32], mx1[32], av2[32], mx2[32];
    __shared__ float h1a[16], h1m[16], h2a[16], h2m[16];
    __shared__ float a1s[32], a2s[32];
    {
        float s1 = 0.f, m1 = -1e30f, s2 = 0.f, m2 = -1e30f;
        for (int chn = 0; chn < NCH; chn++) {
            s1 += g_pf_sum[((size_t)b * NCH + chn) * 32 + c];
            m1 = fmaxf(m1, g_pf_max[((size_t)b * NCH + chn) * 32 + c]);
            s2 += g_pf_sum[(size_t)(BN * NCH * 32) + ((size_t)b * NCH + chn) * 32 + c];
            m2 = fmaxf(m2, g_pf_max[(size_t)(BN * NCH * 32) + ((size_t)b * NCH + chn) * 32 + c]);
        }
        av1[c] = s1 * (1.f / LN); mx1[c] = m1;
        av2[c] = s2 * (1.f / LN); mx2[c] = m2;
    }
    __syncthreads();
    if (c < 16) {
        float s1 = a1b[c], s2 = m1b[c], s3 = a2b[c], s4 = m2b[c];
        for (int j = 0; j < 32; j++) {
            s1 += a1w[c * 32 + j] * av1[j];
            s2 += m1w[c * 32 + j] * mx1[j];
            s3 += a2w[c * 32 + j] * av2[j];
            s4 += m2w[c * 32 + j] * mx2[j];
        }
        h1a[c] = fmaxf(s1, 0.f); h1m[c] = fmaxf(s2, 0.f);
        h2a[c] = fmaxf(s3, 0.f); h2m[c] = fmaxf(s4, 0.f);
    }
    __syncthreads();
    {
        float s1 = a11b[c] + m11b[c];
        float s2 = a22b[c] + m22b[c];
        for (int j = 0; j < 16; j++) {
            s1 += a11w[c * 16 + j] * h1a[j] + m11w[c * 16 + j] * h1m[j];
            s2 += a22w[c * 16 + j] * h2a[j] + m22w[c * 16 + j] * h2m[j];
        }
        a1s[c] = s1; a2s[c] = s2;
    }
    __syncthreads();
    {
        float ac = a1s[c], m = -1e30f;
        for (int d = 0; d < 32; d++) m = fmaxf(m, ac * a2s[d]);
        float sum = 0.f;
        for (int d = 0; d < 32; d++) sum += expf(ac * a2s[d] - m);
        float inv = 1.f / sum;
        for (int d = 0; d < 32; d++) g_s1[(size_t)b * 1024 + c * 32 + d] = expf(ac * a2s[d] - m) * inv;
    }
    {
        float ac = a2s[c], m = -1e30f;
        for (int d = 0; d < 32; d++) m = fmaxf(m, ac * a1s[d]);
        float sum = 0.f;
        for (int d = 0; d < 32; d++) sum += expf(ac * a1s[d] - m);
        float inv = 1.f / sum;
        for (int d = 0; d < 32; d++) g_s2[(size_t)b * 1024 + c * 32 + d] = expf(ac * a1s[d] - m) * inv;
    }
}

// ---------------- K9: fused s@f + mean/max over C, packed ----------------
__global__ __launch_bounds__(128) void k_gate_pool() {
    __shared__ __align__(16) u64 s1d[1024];
    __shared__ __align__(16) u64 s2d[1024];
    const int b = blockIdx.y, ch = blockIdx.x, tid = threadIdx.x;
    for (int i = tid; i < 1024; i += 128) {
        float a = g_s1[(size_t)b * 1024 + i]; s1d[i] = pk2(a, a);
        float c2 = g_s2[(size_t)b * 1024 + i]; s2d[i] = pk2(c2, c2);
    }
    __syncthreads();
    const int l0 = ch * CHK + tid, l1 = l0 + 128;
    // branch 1
    {
        u64 fp[32];
#pragma unroll
        for (int d = 0; d < 32; d++)
            fp[d] = pk2(g_f1[(size_t)b * CN * LN + (size_t)d * LN + l0],
                        g_f1[(size_t)b * CN * LN + (size_t)d * LN + l1]);
        u64 sump = 0ull;
        float mx0 = -1e30f, mx1 = -1e30f;
#pragma unroll 4
        for (int c = 0; c < 32; c++) {
            u64 a = 0ull;
#pragma unroll
            for (int d = 0; d < 32; d++) a = fma2_(s1d[c * 32 + d], fp[d], a);
            sump = add2_(sump, a);
            float a0, a1; upk2(a, a0, a1);
            mx0 = fmaxf(mx0, a0); mx1 = fmaxf(mx1, a1);
        }
        float s0, s1; upk2(sump, s0, s1);
        g_pooled1[(size_t)b * 2 * LN + l0] = s0 * (1.f / 32.f);
        g_pooled1[(size_t)b * 2 * LN + l1] = s1 * (1.f / 32.f);
        g_pooled1[(size_t)b * 2 * LN + LN + l0] = mx0;
        g_pooled1[(size_t)b * 2 * LN + LN + l1] = mx1;
    }
    // branch 2
    {
        u64 fp[32];
#pragma unroll
        for (int d = 0; d < 32; d++)
            fp[d] = pk2(g_f2[(size_t)b * CN * LN + (size_t)d * LN + l0],
                        g_f2[(size_t)b * CN * LN + (size_t)d * LN + l1]);
        u64 sump = 0ull;
        float mx0 = -1e30f, mx1 = -1e30f;
#pragma unroll 4
        for (int c = 0; c < 32; c++) {
            u64 a = 0ull;
#pragma unroll
            for (int d = 0; d < 32; d++) a = fma2_(s2d[c * 32 + d], fp[d], a);
            sump = add2_(sump, a);
            float a0, a1; upk2(a, a0, a1);
            mx0 = fmaxf(mx0, a0); mx1 = fmaxf(mx1, a1);
        }
        float s0, s1; upk2(sump, s0, s1);
        g_pooled2[(size_t)b * 2 * LN + l0] = s0 * (1.f / 32.f);
        g_pooled2[(size_t)b * 2 * LN + l1] = s1 * (1.f / 32.f);
        g_pooled2[(size_t)b * 2 * LN + LN + l0] = mx0;
        g_pooled2[(size_t)b * 2 * LN + LN + l1] = mx1;
    }
}

// ---------------- K10/K11: 3x3 convs ----------------
__global__ __launch_bounds__(256) void k_conv1(const float* __restrict__ w, const float* __restrict__ bias) {
    const int b = blockIdx.x, gate = blockIdx.y, tid = threadIdx.x;
    const float* pin = (gate ? g_pooled2 : g_pooled1) + (size_t)b * 2 * LN;
    float* yo = (gate ? g_y1b : g_y1a) + (size_t)b * LN;
    float wr[18];
#pragma unroll
    for (int i = 0; i < 18; i++) wr[i] = w[i];
    float bv = bias[0];
    for (int p = tid; p < LN; p += 256) {
        int hh = p / WN, ww = p % WN;
        float acc = bv;
#pragma unroll
        for (int ci = 0; ci < 2; ci++)
#pragma unroll
            for (int kh = 0; kh < 3; kh++) {
                int ih = hh + kh - 1;
                if (ih < 0 || ih >= HN) continue;
#pragma unroll
                for (int kw = 0; kw < 3; kw++) {
                    int iw = ww + kw - 1;
                    if (iw < 0 || iw >= WN) continue;
                    acc += pin[(size_t)ci * LN + ih * WN + iw] * wr[(ci * 3 + kh) * 3 + kw];
                }
            }
        yo[p] = fmaxf(acc, 0.f);
    }
}

__global__ __launch_bounds__(256) void k_conv2(const float* __restrict__ w, const float* __restrict__ bias) {
    const int b = blockIdx.x, gate = blockIdx.y, tid = threadIdx.x;
    const float* yin = (gate ? g_y1b : g_y1a) + (size_t)b * LN;
    float* yo = (gate ? g_y2b : g_y2a) + (size_t)b * LN;
    float wr[9];
#pragma unroll
    for (int i = 0; i < 9; i++) wr[i] = w[i];
    float bv = bias[0];
    for (int p = tid; p < LN; p += 256) {
        int hh = p / WN, ww = p % WN;
        float acc = bv;
#pragma unroll
        for (int kh = 0; kh < 3; kh++) {
            int ih = hh + kh - 1;
            if (ih < 0 || ih >= HN) continue;
#pragma unroll
            for (int kw = 0; kw < 3; kw++) {
                int iw = ww + kw - 1;
                if (iw < 0 || iw >= WN) continue;
                acc += yin[ih * WN + iw] * wr[kh * 3 + kw];
            }
        }
        yo[p] = acc;
    }
}

// ---------------- K12: softmax stats ----------------
__global__ __launch_bounds__(256) void k_gstat() {
    const int b = blockIdx.x, gate = blockIdx.y, tid = threadIdx.x;
    const float* y = (gate ? g_y2b : g_y2a) + (size_t)b * LN;
    __shared__ float sh[256];
    float m = -1e30f;
    for (int i = tid; i < LN; i += 256) m = fmaxf(m, y[i]);
    sh[tid] = m;
    __syncthreads();
    for (int o = 128; o > 0; o >>= 1) { if (tid < o) sh[tid] = fmaxf(sh[tid], sh[tid + o]); __syncthreads(); }
    float gm = sh[0];
    __syncthreads();
    float s = 0.f;
    for (int i = tid; i < LN; i += 256) s += expf(y[i] - gm);
    sh[tid] = s;
    __syncthreads();
    for (int o = 128; o > 0; o >>= 1) { if (tid < o) sh[tid] += sh[tid + o]; __syncthreads(); }
    if (tid == 0) { g_gstat[(b * 2 + gate) * 2] = gm; g_gstat[(b * 2 + gate) * 2 + 1] = sh[0]; }
}

// ---------------- K13: final gated residual combine ----------------
__global__ __launch_bounds__(256) void k_final(float* __restrict__ out) {
    const int NT4 = BN * CN * LN / 4;
    int i4 = blockIdx.x * 256 + threadIdx.x;
    if (i4 >= NT4) return;
    size_t i = (size_t)i4 * 4;
    int b = (int)(i / (CN * LN));
    int rem = (int)(i - (size_t)b * CN * LN);
    int l = rem % LN;
    float4 f1v = *(const float4*)(g_f1 + i);
    float4 f2v = *(const float4*)(g_f2 + i);
    float4 y1v = *(const float4*)(g_y2a + (size_t)b * LN + l);
    float4 y2v = *(const float4*)(g_y2b + (size_t)b * LN + l);
    float m1 = g_gstat[b * 4 + 0], s1i = 1.f / g_gstat[b * 4 + 1];
    float m2 = g_gstat[b * 4 + 2], s2i = 1.f / g_gstat[b * 4 + 3];
    float4 o;
    o.x = f1v.x * (1.f + expf(y1v.x - m1) * s1i) + f2v.x * (1.f + expf(y2v.x - m2) * s2i);
    o.y = f1v.y * (1.f + expf(y1v.y - m1) * s1i) + f2v.y * (1.f + expf(y2v.y - m2) * s2i);
    o.z = f1v.z * (1.f + expf(y1v.z - m1) * s1i) + f2v.z * (1.f + expf(y2v.z - m2) * s2i);
    o.w = f1v.w * (1.f + expf(y1v.w - m1) * s1i) + f2v.w * (1.f + expf(y2v.w - m2) * s2i);
    *(float4*)(out + i) = o;
}

// ---------------- launch ----------------
extern "C" void kernel_launch(void* const* d_in, const int* in_sizes, int n_in,
                              void* d_out, int out_size) {
    const float* rgb     = (const float*)d_in[0];
    const float* freq    = (const float*)d_in[1];
    const float* la_qkv  = (const float*)d_in[2];
    const float* la_pw   = (const float*)d_in[3];
    const float* la_pb   = (const float*)d_in[4];
    const float* la_dw   = (const float*)d_in[5];
    const float* xa_qkv  = (const float*)d_in[6];
    const float* xa_temp = (const float*)d_in[7];
    const float* xa_pw   = (const float*)d_in[8];
    const float* xa_pb   = (const float*)d_in[9];
    const float* c1w     = (const float*)d_in[10];
    const float* c1b     = (const float*)d_in[11];
    const float* c2w     = (const float*)d_in[12];
    const float* c2b     = (const float*)d_in[13];
    const float* avg1_w  = (const float*)d_in[14];
    const float* avg1_b  = (const float*)d_in[15];
    const float* max1_w  = (const float*)d_in[16];
    const float* max1_b  = (const float*)d_in[17];
    const float* avg2_w  = (const float*)d_in[18];
    const float* avg2_b  = (const float*)d_in[19];
    const float* max2_w  = (const float*)d_in[20];
    const float* max2_b  = (const float*)d_in[21];
    const float* avg11_w = (const float*)d_in[22];
    const float* avg11_b = (const float*)d_in[23];
    const float* max11_w = (const float*)d_in[24];
    const float* max11_b = (const float*)d_in[25];
    const float* avg22_w = (const float*)d_in[26];
    const float* avg22_b = (const float*)d_in[27];
    const float* max22_w = (const float*)d_in[28];
    const float* max22_b = (const float*)d_in[29];
    float* out = (float*)d_out;

    static int smem_set = 0;
    if (!smem_set) {
        cudaFuncSetAttribute(k_la_pass2, cudaFuncAttributeMaxDynamicSharedMemorySize, LA2_SMEM);
        smem_set = 1;
    }

    dim3 gBL(NCH, BN);
    k_la_pass1<<<gBL, 128>>>(rgb, la_qkv);
    k_la_reduce<<<(BN * HEADSN * 16 + 255) / 256, 256>>>();
    k_la_pass2<<<gBL, 128, LA2_SMEM>>>(rgb, la_qkv, la_pw, la_pb, la_dw);
    k_xca_pass1<<<gBL, 128>>>(freq, xa_qkv);
    k_xca_attn<<<2, 256>>>(xa_temp);
    k_xca_pass2<<<gBL, 128>>>(freq, xa_qkv, xa_pw, xa_pb);
    k_cafm_vec<<<BN, 32>>>(avg1_w, avg1_b, max1_w, max1_b,
                           avg2_w, avg2_b, max2_w, max2_b,
                           avg11_w, avg11_b, max11_w, max11_b,
                           avg22_w, avg22_b, max22_w, max22_b);
    k_gate_pool<<<gBL, 128>>>();
    k_conv1<<<dim3(BN, 2), 256>>>(c1w, c1b);
    k_conv2<<<dim3(BN, 2), 256>>>(c2w, c2b);
    k_gstat<<<dim3(BN, 2), 256>>>();
    k_final<<<(BN * CN * LN / 4 + 255) / 256, 256>>>(out);
}